// round 15
// baseline (speedup 1.0000x reference)
#include <cuda_runtime.h>
#include <cuda_fp16.h>
#include <cstdint>

// Q4 group-quantized linear: out = x @ W^T + bias (harness promotes fp16 -> fp32)
// compute_103 toolchain => no tcgen05; HMMA mma.sync path.
// R15 = R14 + ks-level software pipelining (double-buffered LDSM fragments):
//      preprocess dequantizes W to fp16 (90 MB); GEMM is a plain fp16 GEMM,
//      CTA 128x256, BK=64, 512 thr (16 warps 2m x 8n, warp 64x32), 3-stage cp.async.

#define M_TOTAL 8192
#define K_TOTAL 4096
#define N_TOTAL 11008
#define BM 128
#define BN 256
#define BK 64
#define NKT (K_TOTAL / BK)         // 64
#define LDS 72                     // halves per smem row (144B stride, conflict-free)
#define A_STAGE_H (BM * LDS)       // 9216 halves
#define B_STAGE_H (BN * LDS)       // 18432 halves
#define STAGE_H (A_STAGE_H + B_STAGE_H)
#define NSTAGE 3
#define SMEM_BYTES (NSTAGE * STAGE_H * 2)   // 165888 B
#define N_GROUPS 352256

// ---- scratch (device globals; no runtime allocation) ----
__device__ __align__(16) __half g_x16[(size_t)M_TOTAL * K_TOTAL];   // 64 MB
__device__ __align__(16) __half g_w16[(size_t)N_TOTAL * K_TOTAL];   // 90 MB

// ---- preprocess: fp32 x -> fp16 ----
__global__ void convert_x_kernel(const float* __restrict__ x) {
    size_t base = ((size_t)blockIdx.x * blockDim.x + threadIdx.x) * 8;
    float4 a = *(const float4*)&x[base];
    float4 b = *(const float4*)&x[base + 4];
    __half2 h[4] = { __floats2half2_rn(a.x, a.y), __floats2half2_rn(a.z, a.w),
                     __floats2half2_rn(b.x, b.y), __floats2half2_rn(b.z, b.w) };
    *(uint4*)&g_x16[base] = *(uint4*)h;
}

// ---- preprocess: dequantize W to fp16 (one thread per 128-elem group) ----
__global__ void dequant_w_kernel(const int* __restrict__ qw,
                                 const float* __restrict__ scales,
                                 const float* __restrict__ zeros) {
    int g = blockIdx.x * blockDim.x + threadIdx.x;      // 0 .. N_GROUPS-1
    float s = scales[g];
    float z = zeros[g];
    const int4* src = (const int4*)(qw + (size_t)g * 64);
    uint4* dst = (uint4*)(g_w16 + (size_t)g * 128);
    #pragma unroll
    for (int q = 0; q < 16; ++q) {
        int4 v = src[q];
        int b[4] = { v.x & 0xFF, v.y & 0xFF, v.z & 0xFF, v.w & 0xFF };
        __half2 h[4];
        #pragma unroll
        for (int i = 0; i < 4; ++i) {
            float lo = (float)((b[i] & 15) - 8) * s + z;
            float hi = (float)(((b[i] >> 4) & 15) - 8) * s + z;
            h[i] = __floats2half2_rn(lo, hi);
        }
        dst[q] = *(uint4*)h;
    }
}

__global__ __launch_bounds__(512, 1)
void q4gemm_kernel(const float* __restrict__ bias,
                   float*       __restrict__ out)
{
    extern __shared__ __half smem[];   // [NSTAGE][STAGE_H]: A then B per stage

    const int tid  = threadIdx.x;
    const int wid  = tid >> 5;         // 0..15
    const int lane = tid & 31;
    const int warp_m = wid & 1;        // 0..1 (64 rows)
    const int warp_n = wid >> 1;       // 0..7 (32 cols)
    const int m0 = blockIdx.y * BM;
    const int n0 = blockIdx.x * BN;

    float acc[4][4][4];
    #pragma unroll
    for (int mi = 0; mi < 4; ++mi)
        #pragma unroll
        for (int ni = 0; ni < 4; ++ni)
            #pragma unroll
            for (int r = 0; r < 4; ++r)
                acc[mi][ni][r] = 0.0f;

    auto issue_stage = [&](int kt, int st) {
        __half* sA = smem + st * STAGE_H;
        __half* sB = sA + A_STAGE_H;
        const __half* asrc = g_x16 + (size_t)m0 * K_TOTAL + kt * BK;
        const __half* bsrc = g_w16 + (size_t)n0 * K_TOTAL + kt * BK;
        #pragma unroll
        for (int i = 0; i < 2; ++i) {
            int u = tid + i * 512;
            int r = u >> 3;
            int c = (u & 7) << 3;
            uint32_t d = (uint32_t)__cvta_generic_to_shared(sA + r * LDS + c);
            asm volatile("cp.async.cg.shared.global [%0], [%1], 16;"
                         :: "r"(d), "l"(asrc + (size_t)r * K_TOTAL + c));
        }
        #pragma unroll
        for (int i = 0; i < 4; ++i) {
            int u = tid + i * 512;
            int r = u >> 3;
            int c = (u & 7) << 3;
            uint32_t d = (uint32_t)__cvta_generic_to_shared(sB + r * LDS + c);
            asm volatile("cp.async.cg.shared.global [%0], [%1], 16;"
                         :: "r"(d), "l"(bsrc + (size_t)r * K_TOTAL + c));
        }
        asm volatile("cp.async.commit_group;");
    };

    // fragment loaders (per ks) — proven R6/R7/R14 layouts
    auto load_a = [&](const __half* cA, int ks, uint32_t af[4][4]) {
        #pragma unroll
        for (int mi = 0; mi < 4; ++mi) {
            int row = warp_m * 64 + mi * 16 + (lane & 15);
            int col = ks * 16 + ((lane >> 4) << 3);
            uint32_t addr = (uint32_t)__cvta_generic_to_shared(cA + row * LDS + col);
            asm volatile(
                "ldmatrix.sync.aligned.m8n8.x4.shared.b16 {%0,%1,%2,%3}, [%4];"
                : "=r"(af[mi][0]), "=r"(af[mi][1]),
                  "=r"(af[mi][2]), "=r"(af[mi][3])
                : "r"(addr));
        }
    };
    auto load_b = [&](const __half* cB, int ks, uint32_t bf[4][2]) {
        #pragma unroll
        for (int np = 0; np < 2; ++np) {
            int msel = lane >> 3;               // 0..3
            int row = warp_n * 32 + np * 16 + ((msel >> 1) << 3) + (lane & 7);
            int col = ks * 16 + ((msel & 1) << 3);
            uint32_t addr = (uint32_t)__cvta_generic_to_shared(cB + row * LDS + col);
            asm volatile(
                "ldmatrix.sync.aligned.m8n8.x4.shared.b16 {%0,%1,%2,%3}, [%4];"
                : "=r"(bf[np * 2][0]),     "=r"(bf[np * 2][1]),
                  "=r"(bf[np * 2 + 1][0]), "=r"(bf[np * 2 + 1][1])
                : "r"(addr));
        }
    };

    // ---- prologue: stages 0,1 in flight ----
    issue_stage(0, 0);
    issue_stage(1, 1);

    uint32_t af[2][4][4];
    uint32_t bf[2][4][2];

    for (int kt = 0; kt < NKT; ++kt) {
        const int cur = kt % NSTAGE;

        asm volatile("cp.async.wait_group 1;");
        __syncthreads();

        if (kt + 2 < NKT) issue_stage(kt + 2, (kt + 2) % NSTAGE);

        const __half* cA = smem + cur * STAGE_H;
        const __half* cB = cA + A_STAGE_H;

        // software pipeline over ks: prefetch ks+1 fragments before MMA(ks)
        load_a(cA, 0, af[0]);
        load_b(cB, 0, bf[0]);
        #pragma unroll
        for (int ks = 0; ks < 4; ++ks) {
            const int c = ks & 1;
            const int n = c ^ 1;
            if (ks < 3) {
                load_a(cA, ks + 1, af[n]);
                load_b(cB, ks + 1, bf[n]);
            }
            #pragma unroll
            for (int mi = 0; mi < 4; ++mi)
                #pragma unroll
                for (int ni = 0; ni < 4; ++ni)
                    asm volatile(
                        "mma.sync.aligned.m16n8k16.row.col.f32.f16.f16.f32 "
                        "{%0,%1,%2,%3}, {%4,%5,%6,%7}, {%8,%9}, {%0,%1,%2,%3};"
                        : "+f"(acc[mi][ni][0]), "+f"(acc[mi][ni][1]),
                          "+f"(acc[mi][ni][2]), "+f"(acc[mi][ni][3])
                        : "r"(af[c][mi][0]), "r"(af[c][mi][1]),
                          "r"(af[c][mi][2]), "r"(af[c][mi][3]),
                          "r"(bf[c][ni][0]), "r"(bf[c][ni][1]));
        }
    }

    // ---- epilogue: bias + fp16 rounding (match reference), fp32 store ----
    #pragma unroll
    for (int mi = 0; mi < 4; ++mi) {
        #pragma unroll
        for (int ni = 0; ni < 4; ++ni) {
            int m = m0 + warp_m * 64 + mi * 16 + (lane >> 2);
            int n = n0 + warp_n * 32 + ni * 8 + (lane & 3) * 2;
            float b0 = bias[n];
            float b1 = bias[n + 1];
            float2 r0 = make_float2(__half2float(__float2half(acc[mi][ni][0] + b0)),
                                    __half2float(__float2half(acc[mi][ni][1] + b1)));
            float2 r1 = make_float2(__half2float(__float2half(acc[mi][ni][2] + b0)),
                                    __half2float(__float2half(acc[mi][ni][3] + b1)));
            *(float2*)&out[(size_t)m * N_TOTAL + n]       = r0;
            *(float2*)&out[(size_t)(m + 8) * N_TOTAL + n] = r1;
        }
    }
}

extern "C" void kernel_launch(void* const* d_in, const int* in_sizes, int n_in,
                              void* d_out, int out_size)
{
    const float* x      = (const float*)d_in[0];
    const int*   qw     = (const int*)  d_in[1];
    const float* scales = (const float*)d_in[2];
    const float* zeros  = (const float*)d_in[3];
    const float* bias   = (const float*)d_in[4];
    float*       out    = (float*)d_out;

    cudaFuncSetAttribute(q4gemm_kernel,
                         cudaFuncAttributeMaxDynamicSharedMemorySize, SMEM_BYTES);

    convert_x_kernel<<<(M_TOTAL * (size_t)K_TOTAL) / 8 / 256, 256>>>(x);
    dequant_w_kernel<<<N_GROUPS / 256, 256>>>(qw, scales, zeros);

    dim3 grid(N_TOTAL / BN, M_TOTAL / BM);   // 43 x 64
    q4gemm_kernel<<<grid, 512, SMEM_BYTES>>>(bias, out);
}

// round 16
// speedup vs baseline: 1.1219x; 1.1219x over previous
#include <cuda_runtime.h>
#include <cuda_fp16.h>
#include <cstdint>

// Q4 group-quantized linear: out = x @ W^T + bias (harness promotes fp16 -> fp32)
// compute_103 toolchain => no tcgen05; HMMA mma.sync path.
// R16 = R14 preprocessing (W dequantized to fp16 offline) x R4 execution shape:
//      CTA 128x128, BK=64, 256 thr (8 warps 2m x 4n, warp 64x32),
//      3-stage cp.async pipeline, 110.6 KB smem -> 2 CTAs/SM (phase-interleaved).

#define M_TOTAL 8192
#define K_TOTAL 4096
#define N_TOTAL 11008
#define BM 128
#define BN 128
#define BK 64
#define NKT (K_TOTAL / BK)         // 64
#define LDS 72                     // halves per smem row (144B stride, conflict-free)
#define A_STAGE_H (BM * LDS)       // 9216 halves
#define B_STAGE_H (BN * LDS)       // 9216 halves
#define STAGE_H (A_STAGE_H + B_STAGE_H)
#define NSTAGE 3
#define SMEM_BYTES (NSTAGE * STAGE_H * 2)   // 110592 B
#define N_GROUPS 352256

// ---- scratch (device globals; no runtime allocation) ----
__device__ __align__(16) __half g_x16[(size_t)M_TOTAL * K_TOTAL];   // 64 MB
__device__ __align__(16) __half g_w16[(size_t)N_TOTAL * K_TOTAL];   // 90 MB

// ---- preprocess: fp32 x -> fp16 ----
__global__ void convert_x_kernel(const float* __restrict__ x) {
    size_t base = ((size_t)blockIdx.x * blockDim.x + threadIdx.x) * 8;
    float4 a = *(const float4*)&x[base];
    float4 b = *(const float4*)&x[base + 4];
    __half2 h[4] = { __floats2half2_rn(a.x, a.y), __floats2half2_rn(a.z, a.w),
                     __floats2half2_rn(b.x, b.y), __floats2half2_rn(b.z, b.w) };
    *(uint4*)&g_x16[base] = *(uint4*)h;
}

// ---- preprocess: dequantize W to fp16 (one thread per 128-elem group) ----
// Matches reference: w16 = fp16( fp32(n-8) * s + z ), s,z fp32.
__global__ void dequant_w_kernel(const int* __restrict__ qw,
                                 const float* __restrict__ scales,
                                 const float* __restrict__ zeros) {
    int g = blockIdx.x * blockDim.x + threadIdx.x;      // 0 .. N_GROUPS-1
    float s = scales[g];
    float z = zeros[g];
    const int4* src = (const int4*)(qw + (size_t)g * 64);
    uint4* dst = (uint4*)(g_w16 + (size_t)g * 128);
    #pragma unroll
    for (int q = 0; q < 16; ++q) {
        int4 v = src[q];
        int b[4] = { v.x & 0xFF, v.y & 0xFF, v.z & 0xFF, v.w & 0xFF };
        __half2 h[4];
        #pragma unroll
        for (int i = 0; i < 4; ++i) {
            float lo = (float)((b[i] & 15) - 8) * s + z;
            float hi = (float)(((b[i] >> 4) & 15) - 8) * s + z;
            h[i] = __floats2half2_rn(lo, hi);
        }
        dst[q] = *(uint4*)h;
    }
}

__global__ __launch_bounds__(256, 2)
void q4gemm_kernel(const float* __restrict__ bias,
                   float*       __restrict__ out)
{
    extern __shared__ __half smem[];   // [NSTAGE][STAGE_H]: A then B per stage

    const int tid  = threadIdx.x;
    const int wid  = tid >> 5;         // 0..7
    const int lane = tid & 31;
    const int warp_m = wid & 1;        // 0..1 (64 rows)
    const int warp_n = wid >> 1;       // 0..3 (32 cols)
    const int m0 = blockIdx.y * BM;
    const int n0 = blockIdx.x * BN;

    float acc[4][4][4];
    #pragma unroll
    for (int mi = 0; mi < 4; ++mi)
        #pragma unroll
        for (int ni = 0; ni < 4; ++ni)
            #pragma unroll
            for (int r = 0; r < 4; ++r)
                acc[mi][ni][r] = 0.0f;

    auto issue_stage = [&](int kt, int st) {
        __half* sA = smem + st * STAGE_H;
        __half* sB = sA + A_STAGE_H;
        const __half* asrc = g_x16 + (size_t)m0 * K_TOTAL + kt * BK;
        const __half* bsrc = g_w16 + (size_t)n0 * K_TOTAL + kt * BK;
        // A: 1024 16B chunks, 4 per thread
        #pragma unroll
        for (int i = 0; i < 4; ++i) {
            int u = tid + i * 256;
            int r = u >> 3;
            int c = (u & 7) << 3;
            uint32_t d = (uint32_t)__cvta_generic_to_shared(sA + r * LDS + c);
            asm volatile("cp.async.cg.shared.global [%0], [%1], 16;"
                         :: "r"(d), "l"(asrc + (size_t)r * K_TOTAL + c));
        }
        // B: 1024 16B chunks, 4 per thread
        #pragma unroll
        for (int i = 0; i < 4; ++i) {
            int u = tid + i * 256;
            int r = u >> 3;
            int c = (u & 7) << 3;
            uint32_t d = (uint32_t)__cvta_generic_to_shared(sB + r * LDS + c);
            asm volatile("cp.async.cg.shared.global [%0], [%1], 16;"
                         :: "r"(d), "l"(bsrc + (size_t)r * K_TOTAL + c));
        }
        asm volatile("cp.async.commit_group;");
    };

    // ---- prologue: stages 0,1 in flight ----
    issue_stage(0, 0);
    issue_stage(1, 1);

    for (int kt = 0; kt < NKT; ++kt) {
        const int cur = kt % NSTAGE;

        asm volatile("cp.async.wait_group 1;");
        __syncthreads();

        if (kt + 2 < NKT) issue_stage(kt + 2, (kt + 2) % NSTAGE);

        const __half* cA = smem + cur * STAGE_H;
        const __half* cB = cA + A_STAGE_H;

        #pragma unroll
        for (int ks = 0; ks < 4; ++ks) {
            uint32_t af[4][4];
            uint32_t bf[4][2];
            #pragma unroll
            for (int mi = 0; mi < 4; ++mi) {
                int row = warp_m * 64 + mi * 16 + (lane & 15);
                int col = ks * 16 + ((lane >> 4) << 3);
                uint32_t addr = (uint32_t)__cvta_generic_to_shared(cA + row * LDS + col);
                asm volatile(
                    "ldmatrix.sync.aligned.m8n8.x4.shared.b16 {%0,%1,%2,%3}, [%4];"
                    : "=r"(af[mi][0]), "=r"(af[mi][1]),
                      "=r"(af[mi][2]), "=r"(af[mi][3])
                    : "r"(addr));
            }
            // B: two x4 ldmatrix ops -> 4 n-tiles (validated R4/R7/R14 layout)
            #pragma unroll
            for (int np = 0; np < 2; ++np) {
                int msel = lane >> 3;               // 0..3
                int row = warp_n * 32 + np * 16 + ((msel >> 1) << 3) + (lane & 7);
                int col = ks * 16 + ((msel & 1) << 3);
                uint32_t addr = (uint32_t)__cvta_generic_to_shared(cB + row * LDS + col);
                asm volatile(
                    "ldmatrix.sync.aligned.m8n8.x4.shared.b16 {%0,%1,%2,%3}, [%4];"
                    : "=r"(bf[np * 2][0]),     "=r"(bf[np * 2][1]),
                      "=r"(bf[np * 2 + 1][0]), "=r"(bf[np * 2 + 1][1])
                    : "r"(addr));
            }
            #pragma unroll
            for (int mi = 0; mi < 4; ++mi)
                #pragma unroll
                for (int ni = 0; ni < 4; ++ni)
                    asm volatile(
                        "mma.sync.aligned.m16n8k16.row.col.f32.f16.f16.f32 "
                        "{%0,%1,%2,%3}, {%4,%5,%6,%7}, {%8,%9}, {%0,%1,%2,%3};"
                        : "+f"(acc[mi][ni][0]), "+f"(acc[mi][ni][1]),
                          "+f"(acc[mi][ni][2]), "+f"(acc[mi][ni][3])
                        : "r"(af[mi][0]), "r"(af[mi][1]),
                          "r"(af[mi][2]), "r"(af[mi][3]),
                          "r"(bf[ni][0]), "r"(bf[ni][1]));
        }
    }

    // ---- epilogue: bias + fp16 rounding (match reference), fp32 store ----
    #pragma unroll
    for (int mi = 0; mi < 4; ++mi) {
        #pragma unroll
        for (int ni = 0; ni < 4; ++ni) {
            int m = m0 + warp_m * 64 + mi * 16 + (lane >> 2);
            int n = n0 + warp_n * 32 + ni * 8 + (lane & 3) * 2;
            float b0 = bias[n];
            float b1 = bias[n + 1];
            float2 r0 = make_float2(__half2float(__float2half(acc[mi][ni][0] + b0)),
                                    __half2float(__float2half(acc[mi][ni][1] + b1)));
            float2 r1 = make_float2(__half2float(__float2half(acc[mi][ni][2] + b0)),
                                    __half2float(__float2half(acc[mi][ni][3] + b1)));
            *(float2*)&out[(size_t)m * N_TOTAL + n]       = r0;
            *(float2*)&out[(size_t)(m + 8) * N_TOTAL + n] = r1;
        }
    }
}

extern "C" void kernel_launch(void* const* d_in, const int* in_sizes, int n_in,
                              void* d_out, int out_size)
{
    const float* x      = (const float*)d_in[0];
    const int*   qw     = (const int*)  d_in[1];
    const float* scales = (const float*)d_in[2];
    const float* zeros  = (const float*)d_in[3];
    const float* bias   = (const float*)d_in[4];
    float*       out    = (float*)d_out;

    cudaFuncSetAttribute(q4gemm_kernel,
                         cudaFuncAttributeMaxDynamicSharedMemorySize, SMEM_BYTES);

    convert_x_kernel<<<(M_TOTAL * (size_t)K_TOTAL) / 8 / 256, 256>>>(x);
    dequant_w_kernel<<<N_GROUPS / 256, 256>>>(qw, scales, zeros);

    dim3 grid(N_TOTAL / BN, M_TOTAL / BM);   // 86 x 64
    q4gemm_kernel<<<grid, 256, SMEM_BYTES>>>(bias, out);
}